// round 17
// baseline (speedup 1.0000x reference)
#include <cuda_runtime.h>

typedef unsigned long long u64;

#define HDIM  64
#define IDIM  8
#define KDIM  72          // 64 h + 8 x folded into one reduction
#define KK    36          // KDIM/2
#define NTHR  256
#define NPAIR 8           // batch pairs per CTA
#define NB    16          // batches per CTA
#define PPT   4           // pairs per thread (all pairs of the 128-thread group)

// SMEM (dynamic), per CTA (<= ~113KB so 2 CTAs/SM fit):
//  wsmA[kk=36][j=128] float2 : 36864 B   row A = u + 128*gh      (i or g)
//  wsmB[kk=36][j=128] float2 : 36864 B   row B = u + 64 + 128*gh (f or o)
//  hx[2][NPAIR][KDIM] u64    :  9216 B
#define WSMA_BYTES (KK * 128 * 8)
#define WSMB_BYTES (KK * 128 * 8)
#define HX_BYTES   (2 * NPAIR * KDIM * 8)
#define SMEM_BYTES (WSMA_BYTES + WSMB_BYTES + HX_BYTES)

// ---- packed f32x2 helpers (Blackwell sm_100a) ----
__device__ __forceinline__ u64 ffma2(u64 a, u64 b, u64 c) {
    u64 r;
    asm("fma.rn.f32x2 %0, %1, %2, %3;" : "=l"(r) : "l"(a), "l"(b), "l"(c));
    return r;
}
__device__ __forceinline__ u64 pack2(float x, float y) {
    u64 r;
    asm("mov.b64 %0, {%1, %2};" : "=l"(r) : "f"(x), "f"(y));
    return r;
}
__device__ __forceinline__ void unpack2(u64 v, float& lo, float& hi) {
    asm("mov.b64 {%0, %1}, %2;" : "=f"(lo), "=f"(hi) : "l"(v));
}

// ---- activations: MUFU ex2 + MUFU rcp; ~2 ulp ----
__device__ __forceinline__ float sigm_f(float x) {
    return __fdividef(1.0f, 1.0f + __expf(-x));
}
__device__ __forceinline__ float tanh_f(float x) {
    return fmaf(2.0f, __fdividef(1.0f, 1.0f + __expf(-2.0f * x)), -1.0f);
}

__global__ void __launch_bounds__(NTHR, 2) lstm_persistent_kernel(
    const float* __restrict__ x,      // [B, T, I]
    const float* __restrict__ Wih,    // [4H, I]
    const float* __restrict__ Whh,    // [4H, H]
    const float* __restrict__ bih,    // [4H]
    const float* __restrict__ bhh,    // [4H]
    const float* __restrict__ Wfc,    // [1, H]
    const float* __restrict__ bfc,    // [1]
    float* __restrict__ out,          // [B, 1]
    int B, int T)
{
    extern __shared__ __align__(16) char smem_raw[];
    float2* wsmA = (float2*)smem_raw;                               // [kk*128 + j]
    float2* wsmB = (float2*)(smem_raw + WSMA_BYTES);                // [kk*128 + j]
    u64*    hxb  = (u64*)(smem_raw + WSMA_BYTES + WSMB_BYTES);      // [buf][pair][KDIM]

    const int tid  = threadIdx.x;
    const int lane = tid & 31;
    const int warp = tid >> 5;        // 0..7
    const int grp  = warp >> 2;       // group 0/1 (4 warps, 128 threads)
    const int wg   = warp & 3;        // warp within group
    const int u    = 16 * wg + (lane >> 1);   // hidden unit 0..63
    const int gh   = lane & 1;        // gate half: 0 -> (i,f), 1 -> (g,o)
    const int jw   = wg * 32 + lane;  // weight column for this thread (0..127)
    const int pb   = grp * PPT;       // group pairs: pb..pb+3
    const int b0   = blockIdx.x * NB;

    // ---- stage permuted weights: column j = (wg, lane) -> rows u+128gh / u+64+128gh ----
    for (int idx = tid; idx < KK * 128; idx += NTHR) {
        const int kk = idx >> 7, j = idx & 127;
        const int ww = j >> 5, ll = j & 31;
        const int uu = 16 * ww + (ll >> 1);
        const int hh = ll & 1;
        const int rowA = uu + 128 * hh;
        const int rowB = uu + 64 + 128 * hh;
        const int k0 = 2 * kk, k1 = 2 * kk + 1;
        float a0 = (k0 < HDIM) ? Whh[rowA * HDIM + k0] : Wih[rowA * IDIM + (k0 - HDIM)];
        float a1 = (k1 < HDIM) ? Whh[rowA * HDIM + k1] : Wih[rowA * IDIM + (k1 - HDIM)];
        float b0w = (k0 < HDIM) ? Whh[rowB * HDIM + k0] : Wih[rowB * IDIM + (k0 - HDIM)];
        float b1w = (k1 < HDIM) ? Whh[rowB * HDIM + k1] : Wih[rowB * IDIM + (k1 - HDIM)];
        wsmA[idx] = make_float2(a0, a1);
        wsmB[idx] = make_float2(b0w, b1w);
    }

    // ---- per-thread biases for own two gate rows ----
    const int rowA = u + 128 * gh;
    const int rowB = u + 64 + 128 * gh;
    const float bA = bih[rowA] + bhh[rowA];
    const float bB = bih[rowB] + bhh[rowB];
    const u64 biasA = pack2(bA, bA);
    const u64 biasB = pack2(bB, bB);

    // ---- zero hx (both buffers) ----
    for (int idx = tid; idx < 2 * NPAIR * KDIM; idx += NTHR) hxb[idx] = 0ull;

    // ---- cell state for the 2 KEPT pairs (gh=0 keeps local 0,1; gh=1 keeps 2,3) ----
    const int kbase = gh * 2;         // first kept local pair
    float ce[2], co[2];
    ce[0] = ce[1] = co[0] = co[1] = 0.0f;

    // ---- group-local x staging (group covers pairs pb..pb+3 = 8 batches) ----
    const int lt = jw;                // local thread id within group, 0..127
    const int xp = pb + (lt >> 4);    // pair (valid when lt < 64)
    const int xe = (lt >> 3) & 1;     // half within pair
    const int xi = lt & 7;            // feature
    const int xbatch = b0 + 2 * xp + xe;
    const bool xok = (lt < 64) && (xbatch < B);
    if (xok) {
        float v = x[((size_t)xbatch * T) * IDIM + xi];
        ((float*)&hxb[xp * KDIM + HDIM + xi])[xe] = v;
    }
    __syncthreads();   // weights + initial state visible

    for (int t = 0; t < T; ++t) {
        // prefetch x(t+1) for own group's pairs
        float xn = 0.0f;
        const bool do_x = (t + 1 < T) && xok;
        if (do_x)
            xn = x[((size_t)xbatch * T + (t + 1)) * IDIM + xi];

        const u64* hcur = hxb + (t & 1) * (NPAIR * KDIM);
        u64*       hnxt = hxb + ((t + 1) & 1) * (NPAIR * KDIM);

        // ---- matvec over KDIM=72: 2 gate rows x 4 pairs = 8 chains ----
        u64 aA[PPT], aB[PPT];
#pragma unroll
        for (int p = 0; p < PPT; ++p) { aA[p] = biasA; aB[p] = biasB; }

#pragma unroll
        for (int kk = 0; kk < KK; ++kk) {
            float2 wa = wsmA[kk * 128 + jw];   // lane-consecutive LDS.64
            float2 wb = wsmB[kk * 128 + jw];
            const u64 wA0 = pack2(wa.x, wa.x);
            const u64 wA1 = pack2(wa.y, wa.y);
            const u64 wB0 = pack2(wb.x, wb.x);
            const u64 wB1 = pack2(wb.y, wb.y);
            ulonglong2 hv[PPT];
#pragma unroll
            for (int p = 0; p < PPT; ++p)
                hv[p] = *(const ulonglong2*)(hcur + (pb + p) * KDIM + 2 * kk);
#pragma unroll
            for (int p = 0; p < PPT; ++p) {
                aA[p] = ffma2(hv[p].x, wA0, aA[p]);
                aA[p] = ffma2(hv[p].y, wA1, aA[p]);
                aB[p] = ffma2(hv[p].x, wB0, aB[p]);
                aB[p] = ffma2(hv[p].y, wB1, aB[p]);
            }
        }

        // stash prefetched x into next buffer (own pairs; read after group barrier)
        if (do_x)
            ((float*)&hnxt[xp * KDIM + HDIM + xi])[xe] = xn;

        // ---- intra-warp gate exchange with partner lane (lane^1): send slots the
        //      partner keeps, receive our kept pairs' missing gate-half ----
        const int s0 = gh ? 0 : 2;    // slots I send = partner's kept pairs
        const u64 eA0 = __shfl_xor_sync(0xFFFFFFFFu, aA[s0], 1);
        const u64 eA1 = __shfl_xor_sync(0xFFFFFFFFu, aA[s0 + 1], 1);
        const u64 eB0 = __shfl_xor_sync(0xFFFFFFFFu, aB[s0], 1);
        const u64 eB1 = __shfl_xor_sync(0xFFFFFFFFu, aB[s0 + 1], 1);
        // gates for kept pair s (local kbase+s):
        //   gh=0: i=aA[s], f=aB[s], g=eA_s, o=eB_s
        //   gh=1: i=eA_s, f=eB_s, g=aA[2+s], o=aB[2+s]
        const u64 gI[2] = { gh ? eA0 : aA[0],  gh ? eA1 : aA[1] };
        const u64 gF[2] = { gh ? eB0 : aB[0],  gh ? eB1 : aB[1] };
        const u64 gG[2] = { gh ? aA[2] : eA0,  gh ? aA[3] : eA1 };
        const u64 gO[2] = { gh ? aB[2] : eB0,  gh ? aB[3] : eB1 };

        // ---- pointwise for kept 2 pairs (4 batch elements) ----
#pragma unroll
        for (int s = 0; s < 2; ++s) {
            float ie, io, fe, fo, ge, go_, oe, oo;
            unpack2(gI[s], ie, io);
            unpack2(gF[s], fe, fo);
            unpack2(gG[s], ge, go_);
            unpack2(gO[s], oe, oo);

            float iv = sigm_f(ie), fv = sigm_f(fe), gv = tanh_f(ge), ov = sigm_f(oe);
            float c  = fmaf(fv, ce[s], iv * gv);
            ce[s] = c;
            float he = ov * tanh_f(c);

            iv = sigm_f(io); fv = sigm_f(fo); gv = tanh_f(go_); ov = sigm_f(oo);
            c  = fmaf(fv, co[s], iv * gv);
            co[s] = c;
            float ho = ov * tanh_f(c);

            hnxt[(pb + kbase + s) * KDIM + u] = pack2(he, ho);
        }

        // ---- group barrier (4 warps, 128 threads): groups free-run vs each other ----
        asm volatile("bar.sync %0, %1;" :: "r"(1 + grp), "r"(128) : "memory");
    }

    __syncthreads();   // FC below reads h across groups

    // ---- final FC: out[b] = h_T . Wfc + bfc ----
    const u64* hfin = hxb + (T & 1) * (NPAIR * KDIM);
    const int nb = min(NB, B - b0);
    if (tid < nb) {
        const int p = tid >> 1, e = tid & 1;
        float s = bfc[0];
#pragma unroll
        for (int k = 0; k < HDIM; ++k)
            s = fmaf(((const float*)&hfin[p * KDIM + k])[e], Wfc[k], s);
        out[b0 + tid] = s;
    }
}

extern "C" void kernel_launch(void* const* d_in, const int* in_sizes, int n_in,
                              void* d_out, int out_size) {
    const float* x    = (const float*)d_in[0];
    const float* Wih  = (const float*)d_in[1];
    const float* Whh  = (const float*)d_in[2];
    const float* bih  = (const float*)d_in[3];
    const float* bhh  = (const float*)d_in[4];
    const float* Wfc  = (const float*)d_in[5];
    const float* bfc  = (const float*)d_in[6];
    float* out = (float*)d_out;

    const int B = out_size;                   // O = 1
    const int T = in_sizes[0] / (B * IDIM);

    cudaFuncSetAttribute(lstm_persistent_kernel,
                         cudaFuncAttributeMaxDynamicSharedMemorySize, SMEM_BYTES);

    const int grid = (B + NB - 1) / NB;       // 256 CTAs -> 2 per SM (most SMs)
    lstm_persistent_kernel<<<grid, NTHR, SMEM_BYTES>>>(x, Wih, Whh, bih, bhh, Wfc, bfc, out, B, T);
}